// round 4
// baseline (speedup 1.0000x reference)
#include <cuda_runtime.h>
#include <cuda_fp16.h>
#include <mma.h>

// ---------------- scratch (device globals; no allocation allowed) ----------
#define NMAX  100032
#define ECAP  1664000

__device__ __half g_h [NMAX * 64];   // GEMM output (pre-scaled by dis[row]), fp16
__device__ __half g_a [NMAX * 64];   // post-aggregation activations, fp16
__device__ float  g_dis[NMAX];
__device__ int    g_cnt[NMAX];
__device__ int    g_rptr[NMAX];
__device__ int    g_col[ECAP];
__device__ int    g_bsum[128];
// split-fp16 weights: W ~= Wh + Wl with residual lo
__device__ __half g_w1h[128 * 64], g_w1l[128 * 64];
__device__ __half g_w2h[64 * 64],  g_w2l[64 * 64];

// ---------------- preprocessing kernels ------------------------------------

__global__ void k_hist(const int* __restrict__ dst, int E) {
    int e = blockIdx.x * 256 + threadIdx.x;
    if (e < E) atomicAdd(&g_cnt[dst[e]], 1);
}

// block-wide exclusive scan helper (blockDim.x == 1024)
__device__ __forceinline__ int blockscan_excl(int v, int* total) {
    __shared__ int ws[32];
    int lane = threadIdx.x & 31, wid = threadIdx.x >> 5;
    int s = v;
#pragma unroll
    for (int o = 1; o < 32; o <<= 1) {
        int t = __shfl_up_sync(0xffffffffu, s, o);
        if (lane >= o) s += t;
    }
    if (lane == 31) ws[wid] = s;
    __syncthreads();
    if (wid == 0) {
        int u = ws[lane];
#pragma unroll
        for (int o = 1; o < 32; o <<= 1) {
            int t = __shfl_up_sync(0xffffffffu, u, o);
            if (lane >= o) u += t;
        }
        ws[lane] = u;
    }
    __syncthreads();
    int incl = s + (wid ? ws[wid - 1] : 0);
    if (total) *total = ws[31];
    return incl - v;
}

__global__ void k_scan1(int n) {
    int i = blockIdx.x * 1024 + threadIdx.x;
    int v = (i < n) ? g_cnt[i] : 0;
    int tot;
    int ex = blockscan_excl(v, &tot);
    if (i < n) g_rptr[i] = ex;
    if (threadIdx.x == 0) g_bsum[blockIdx.x] = tot;
}

// scan of block sums, fused with weight hi/lo splitting (independent work)
__global__ void k_scan2(int nb, const float* __restrict__ W1,
                        const float* __restrict__ W2) {
    int i = threadIdx.x;
    int v = (i < nb) ? g_bsum[i] : 0;   // reads complete before writes (barrier in scan)
    int ex = blockscan_excl(v, nullptr);
    if (i < nb) g_bsum[i] = ex;

    for (int j = threadIdx.x; j < 128 * 64; j += 1024) {
        float w = W1[j];
        __half h = __float2half_rn(w);
        g_w1h[j] = h;
        g_w1l[j] = __float2half_rn(w - __half2float(h));
    }
    for (int j = threadIdx.x; j < 64 * 64; j += 1024) {
        float w = W2[j];
        __half h = __float2half_rn(w);
        g_w2h[j] = h;
        g_w2l[j] = __float2half_rn(w - __half2float(h));
    }
}

// fused: rptr += carry; dis = rsqrt(deg+1)
__global__ void k_scan3dis(int n) {
    int i = blockIdx.x * 1024 + threadIdx.x;
    if (i < n) {
        g_rptr[i] += g_bsum[blockIdx.x];
        g_dis[i] = rsqrtf((float)(g_cnt[i] + 1));   // +1 self loop; always > 0
    }
}

// CSR fill: post-increment rowptr in place. After this, rptr[i] == inclusive
// scan, so row i spans [i ? rptr[i-1] : 0, rptr[i]).
__global__ void k_fill(const int* __restrict__ src, const int* __restrict__ dst, int E) {
    int e = blockIdx.x * 256 + threadIdx.x;
    if (e < E) {
        int d = dst[e];
        int p = atomicAdd(&g_rptr[d], 1);
        g_col[p] = src[e];
    }
}

// ---------------- GEMM via wmma/HMMA, split-fp16 for fp32 accuracy ----------
// H[n,64] = (A[n,K] @ W[K,64]) * dis[row]  -> fp16 g_h
// !HALF_IN (layer 1): A fp32; converted to hi+lo fp16 tiles in smem;
//   D = Ahi*Wh + Ahi*Wl + Alo*Wh   (error ~ eps_fp16^2)
// HALF_IN  (layer 2): A is exact fp16 in g_a; D = A*Wh + A*Wl.
// Block: 64 rows x 64 cols; 8 warps; warp (rt, ch) owns rows rt*16..+15,
// cols ch*32..+31 (two 16x16 accum frags).
template <int K, bool HALF_IN>
__global__ void __launch_bounds__(256) k_gemm_wmma(const float* __restrict__ Ain,
                                                   const __half* __restrict__ Wh,
                                                   const __half* __restrict__ Wl,
                                                   int n) {
    using namespace nvcuda;
    constexpr int LDA = K + 8;
    // layer1: sAh + sAl tiles (reused as float staging after mainloop)
    // layer2: staging only (8 warps x 512 floats = 16 KB)
    __shared__ __align__(16) char smem_raw[HALF_IN ? 16384 : 2 * 64 * LDA * 2];
    __half* sAh = (__half*)smem_raw;
    __half* sAl = sAh + 64 * LDA;

    int tid = threadIdx.x;
    int wid = tid >> 5, lane = tid & 31;
    int rt = wid >> 1, ch = wid & 1;
    int row0 = blockIdx.x * 64;

    if (!HALF_IN) {
        int nv = 64 * (K / 4);
        for (int i = tid; i < nv; i += 256) {
            int row = i / (K / 4), c4 = i % (K / 4);
            int grow = row0 + row;
            float4 v = (grow < n) ? *(const float4*)(Ain + (size_t)grow * K + c4 * 4)
                                  : make_float4(0.f, 0.f, 0.f, 0.f);
            __half hx = __float2half_rn(v.x), hy = __float2half_rn(v.y);
            __half hz = __float2half_rn(v.z), hw = __float2half_rn(v.w);
            __half2* ph = (__half2*)(sAh + row * LDA + c4 * 4);
            ph[0] = __halves2half2(hx, hy);
            ph[1] = __halves2half2(hz, hw);
            __half2* pl = (__half2*)(sAl + row * LDA + c4 * 4);
            pl[0] = __halves2half2(__float2half_rn(v.x - __half2float(hx)),
                                   __float2half_rn(v.y - __half2float(hy)));
            pl[1] = __halves2half2(__float2half_rn(v.z - __half2float(hz)),
                                   __float2half_rn(v.w - __half2float(hw)));
        }
        __syncthreads();
    }

    wmma::fragment<wmma::accumulator, 16, 16, 16, float> c0, c1;
    wmma::fill_fragment(c0, 0.f);
    wmma::fill_fragment(c1, 0.f);

#pragma unroll
    for (int ks = 0; ks < K / 16; ks++) {
        wmma::fragment<wmma::matrix_b, 16, 16, 16, __half, wmma::row_major> bh0, bh1, bl0, bl1;
        wmma::load_matrix_sync(bh0, Wh + ks * 16 * 64 + ch * 32, 64);
        wmma::load_matrix_sync(bh1, Wh + ks * 16 * 64 + ch * 32 + 16, 64);
        wmma::load_matrix_sync(bl0, Wl + ks * 16 * 64 + ch * 32, 64);
        wmma::load_matrix_sync(bl1, Wl + ks * 16 * 64 + ch * 32 + 16, 64);

        if (HALF_IN) {
            wmma::fragment<wmma::matrix_a, 16, 16, 16, __half, wmma::row_major> a;
            wmma::load_matrix_sync(a, g_a + (size_t)(row0 + rt * 16) * 64 + ks * 16, 64);
            wmma::mma_sync(c0, a, bh0, c0);
            wmma::mma_sync(c0, a, bl0, c0);
            wmma::mma_sync(c1, a, bh1, c1);
            wmma::mma_sync(c1, a, bl1, c1);
        } else {
            wmma::fragment<wmma::matrix_a, 16, 16, 16, __half, wmma::row_major> ah, al;
            wmma::load_matrix_sync(ah, sAh + (rt * 16) * LDA + ks * 16, LDA);
            wmma::load_matrix_sync(al, sAl + (rt * 16) * LDA + ks * 16, LDA);
            wmma::mma_sync(c0, ah, bh0, c0);
            wmma::mma_sync(c0, ah, bl0, c0);
            wmma::mma_sync(c0, al, bh0, c0);
            wmma::mma_sync(c1, ah, bh1, c1);
            wmma::mma_sync(c1, ah, bl1, c1);
            wmma::mma_sync(c1, al, bh1, c1);
        }
    }

    if (!HALF_IN) __syncthreads();     // done reading sA; reuse as staging
    float* stage = (float*)smem_raw + wid * 512;    // 16 rows x 32 cols
    wmma::store_matrix_sync(stage, c0, 32, wmma::mem_row_major);
    wmma::store_matrix_sync(stage + 16, c1, 32, wmma::mem_row_major);
    __syncwarp();

    int r = lane >> 1, hf = lane & 1;
    int grow = row0 + rt * 16 + r;
    if (grow < n) {
        float d = g_dis[grow];
        const float* src = stage + r * 32 + hf * 16;
        __half2 hbuf[8];
#pragma unroll
        for (int j = 0; j < 8; j++)
            hbuf[j] = __floats2half2_rn(src[2 * j] * d, src[2 * j + 1] * d);
        uint4* dst = (uint4*)(g_h + (size_t)grow * 64 + ch * 32 + hf * 16);
        dst[0] = ((uint4*)hbuf)[0];
        dst[1] = ((uint4*)hbuf)[1];
    }
}

// ---------------- aggregation: warp per dst node ---------------------------
// out[i] = relu( dis[i] * (h'[i] + sum_{src in nbrs} h'[src]) + bias )
// h' rows are fp16 (128B/row, one half2 per lane). Accumulate fp32.
// FC=true additionally applies the 64->4 FC + bfc and writes float4 per node.
template <bool FC>
__global__ void __launch_bounds__(256) k_agg(const float* __restrict__ bias,
                                             const float* __restrict__ Wfc,
                                             const float* __restrict__ bfc,
                                             float* __restrict__ out, int n) {
    int w = (blockIdx.x * 256 + threadIdx.x) >> 5;
    int lane = threadIdx.x & 31;
    if (w >= n) return;

    int start = w ? __ldg(&g_rptr[w - 1]) : 0;
    int end = __ldg(&g_rptr[w]);

    const __half2* __restrict__ H2 = (const __half2*)g_h;
    float2 acc = __half22float2(H2[(size_t)w * 32 + lane]);   // self loop

    int e = start;
    while (e < end && (e & 3)) {
        float2 v = __half22float2(H2[(size_t)__ldg(&g_col[e]) * 32 + lane]);
        acc.x += v.x; acc.y += v.y;
        e++;
    }
    for (; e + 4 <= end; e += 4) {
        int4 cs = *(const int4*)(g_col + e);   // broadcast LDG.128
        float2 v0 = __half22float2(H2[(size_t)cs.x * 32 + lane]);
        float2 v1 = __half22float2(H2[(size_t)cs.y * 32 + lane]);
        float2 v2 = __half22float2(H2[(size_t)cs.z * 32 + lane]);
        float2 v3 = __half22float2(H2[(size_t)cs.w * 32 + lane]);
        acc.x += (v0.x + v1.x) + (v2.x + v3.x);
        acc.y += (v0.y + v1.y) + (v2.y + v3.y);
    }
    while (e < end) {
        float2 v = __half22float2(H2[(size_t)__ldg(&g_col[e]) * 32 + lane]);
        acc.x += v.x; acc.y += v.y;
        e++;
    }

    float d = g_dis[w];
    float2 b = ((const float2*)bias)[lane];
    float ox = fmaxf(fmaf(acc.x, d, b.x), 0.f);
    float oy = fmaxf(fmaf(acc.y, d, b.y), 0.f);

    if (!FC) {
        ((__half2*)g_a)[(size_t)w * 32 + lane] = __floats2half2_rn(ox, oy);
    } else {
        const float4* Wf = (const float4*)Wfc;   // [64][4]
        float4 w0 = Wf[2 * lane], w1 = Wf[2 * lane + 1];
        float4 y;
        y.x = ox * w0.x + oy * w1.x;
        y.y = ox * w0.y + oy * w1.y;
        y.z = ox * w0.z + oy * w1.z;
        y.w = ox * w0.w + oy * w1.w;
#pragma unroll
        for (int o = 16; o; o >>= 1) {
            y.x += __shfl_xor_sync(0xffffffffu, y.x, o);
            y.y += __shfl_xor_sync(0xffffffffu, y.y, o);
            y.z += __shfl_xor_sync(0xffffffffu, y.z, o);
            y.w += __shfl_xor_sync(0xffffffffu, y.w, o);
        }
        if (lane == 0) {
            float4 bf = *(const float4*)bfc;
            ((float4*)out)[w] = make_float4(y.x + bf.x, y.y + bf.y, y.z + bf.z, y.w + bf.w);
        }
    }
}

// ---------------- launch ----------------------------------------------------

extern "C" void kernel_launch(void* const* d_in, const int* in_sizes, int n_in,
                              void* d_out, int out_size) {
    const float* x   = (const float*)d_in[0];
    const int*   ei  = (const int*)d_in[1];
    const float* W1  = (const float*)d_in[2];
    const float* b1  = (const float*)d_in[3];
    const float* W2  = (const float*)d_in[4];
    const float* b2  = (const float*)d_in[5];
    const float* Wfc = (const float*)d_in[6];
    const float* bfc = (const float*)d_in[7];

    int n = in_sizes[0] / 128;
    int E = in_sizes[1] / 2;
    if (n > NMAX) n = NMAX;
    if (E > ECAP) E = ECAP;
    const int* src = ei;
    const int* dst = ei + E;
    int nb = (n + 1023) / 1024;

    void* cnt_ptr = nullptr;
    cudaGetSymbolAddress(&cnt_ptr, g_cnt);
    cudaMemsetAsync(cnt_ptr, 0, (size_t)n * sizeof(int));

    k_hist<<<(E + 255) / 256, 256>>>(dst, E);
    k_scan1<<<nb, 1024>>>(n);
    k_scan2<<<1, 1024>>>(nb, W1, W2);
    k_scan3dis<<<nb, 1024>>>(n);
    k_fill<<<(E + 255) / 256, 256>>>(src, dst, E);

    const __half *w1h, *w1l, *w2h, *w2l;
    cudaGetSymbolAddress((void**)&w1h, g_w1h);
    cudaGetSymbolAddress((void**)&w1l, g_w1l);
    cudaGetSymbolAddress((void**)&w2h, g_w2h);
    cudaGetSymbolAddress((void**)&w2l, g_w2l);

    int gb = (n + 63) / 64;
    k_gemm_wmma<128, false><<<gb, 256>>>(x, w1h, w1l, n);
    k_agg<false><<<(n + 7) / 8, 256>>>(b1, nullptr, nullptr, nullptr, n);
    k_gemm_wmma<64, true><<<gb, 256>>>(nullptr, w2h, w2l, n);
    k_agg<true><<<(n + 7) / 8, 256>>>(b2, Wfc, bfc, (float*)d_out, n);
}

// round 5
// speedup vs baseline: 1.0440x; 1.0440x over previous
#include <cuda_runtime.h>
#include <cuda_fp16.h>

// ---------------- scratch (device globals; no allocation allowed) ----------
#define NMAX  100032
#define ECAP  1664000

__device__ __half g_h [NMAX * 64];   // GEMM output (pre-scaled by dis[row]), fp16
__device__ __half g_a [NMAX * 64];   // post-aggregation activations, fp16
__device__ float  g_dis[NMAX];
__device__ int    g_cnt[NMAX];
__device__ int    g_rptr[NMAX];      // block-local prefix; carry lives in g_bsum
__device__ int    g_col[ECAP];
__device__ int    g_bsum[128];

// ---------------- preprocessing kernels ------------------------------------

__global__ void k_hist(const int* __restrict__ dst, int E) {
    int e = (blockIdx.x * 256 + threadIdx.x) * 4;
    if (e + 4 <= E) {
        int4 d = *(const int4*)(dst + e);
        atomicAdd(&g_cnt[d.x], 1);
        atomicAdd(&g_cnt[d.y], 1);
        atomicAdd(&g_cnt[d.z], 1);
        atomicAdd(&g_cnt[d.w], 1);
    } else {
        for (; e < E; e++) atomicAdd(&g_cnt[dst[e]], 1);
    }
}

// block-wide exclusive scan helper (blockDim.x == 1024)
__device__ __forceinline__ int blockscan_excl(int v, int* total) {
    __shared__ int ws[32];
    int lane = threadIdx.x & 31, wid = threadIdx.x >> 5;
    int s = v;
#pragma unroll
    for (int o = 1; o < 32; o <<= 1) {
        int t = __shfl_up_sync(0xffffffffu, s, o);
        if (lane >= o) s += t;
    }
    if (lane == 31) ws[wid] = s;
    __syncthreads();
    if (wid == 0) {
        int u = ws[lane];
#pragma unroll
        for (int o = 1; o < 32; o <<= 1) {
            int t = __shfl_up_sync(0xffffffffu, u, o);
            if (lane >= o) u += t;
        }
        ws[lane] = u;
    }
    __syncthreads();
    int incl = s + (wid ? ws[wid - 1] : 0);
    if (total) *total = ws[31];
    return incl - v;
}

// per-block exclusive scan of cnt -> rptr (local), block totals -> bsum,
// fused with dis = rsqrt(deg+1)
__global__ void k_scan1(int n) {
    int i = blockIdx.x * 1024 + threadIdx.x;
    int v = (i < n) ? g_cnt[i] : 0;
    int tot;
    int ex = blockscan_excl(v, &tot);
    if (i < n) {
        g_rptr[i] = ex;
        g_dis[i] = rsqrtf((float)(v + 1));   // +1 self loop; always > 0
    }
    if (threadIdx.x == 0) g_bsum[blockIdx.x] = tot;
}

// exclusive scan of block sums (single block)
__global__ void k_scan2(int nb) {
    int i = threadIdx.x;
    int v = (i < nb) ? g_bsum[i] : 0;   // reads complete before writes (barrier in scan)
    int ex = blockscan_excl(v, nullptr);
    if (i < nb) g_bsum[i] = ex;
}

// CSR fill. Slot = local post-increment + block carry. After this,
// g_rptr[i] == local inclusive prefix; global inclusive = rptr[i]+bsum[i>>10].
__global__ void k_fill(const int* __restrict__ src, const int* __restrict__ dst, int E) {
    int e = (blockIdx.x * 256 + threadIdx.x) * 4;
    if (e + 4 <= E) {
        int4 d = *(const int4*)(dst + e);
        int4 s = *(const int4*)(src + e);
        g_col[atomicAdd(&g_rptr[d.x], 1) + g_bsum[d.x >> 10]] = s.x;
        g_col[atomicAdd(&g_rptr[d.y], 1) + g_bsum[d.y >> 10]] = s.y;
        g_col[atomicAdd(&g_rptr[d.z], 1) + g_bsum[d.z >> 10]] = s.z;
        g_col[atomicAdd(&g_rptr[d.w], 1) + g_bsum[d.w >> 10]] = s.w;
    } else {
        for (; e < E; e++) {
            int d = dst[e];
            g_col[atomicAdd(&g_rptr[d], 1) + g_bsum[d >> 10]] = src[e];
        }
    }
}

// ---------------- GEMM: H[n,64] = (A[n,K] @ W[K,64]) * dis[row] -> fp16 -----
// Register-blocked: 4 rows x 8 cols per thread; W tile in smem. (R2 version)
template <int K, bool HALF_IN>
__global__ void __launch_bounds__(256) k_gemm(const float* __restrict__ Ain,
                                              const float* __restrict__ W, int n) {
    __shared__ float sW[K * 64];
    int tid = threadIdx.x;
    for (int i = tid; i < K * 16; i += 256)
        ((float4*)sW)[i] = ((const float4*)W)[i];
    __syncthreads();

    int cc = tid & 7;            // 8 col-chunks of 8
    int rg = tid >> 3;           // 32 row-groups of 4
    int row0 = blockIdx.x * 128 + rg * 4;

    float acc[4][8];
#pragma unroll
    for (int r = 0; r < 4; r++)
#pragma unroll
        for (int c = 0; c < 8; c++) acc[r][c] = 0.f;

    bool ok[4];
#pragma unroll
    for (int r = 0; r < 4; r++) ok[r] = (row0 + r) < n;

    for (int k0 = 0; k0 < K; k0 += 8) {
        float a8[4][8];
#pragma unroll
        for (int r = 0; r < 4; r++) {
            if (HALF_IN) {
                uint4 u = ok[r] ? *(const uint4*)(g_a + (size_t)(row0 + r) * K + k0)
                                : make_uint4(0, 0, 0, 0);
                float2 f0 = __half22float2(*(__half2*)&u.x);
                float2 f1 = __half22float2(*(__half2*)&u.y);
                float2 f2 = __half22float2(*(__half2*)&u.z);
                float2 f3 = __half22float2(*(__half2*)&u.w);
                a8[r][0] = f0.x; a8[r][1] = f0.y; a8[r][2] = f1.x; a8[r][3] = f1.y;
                a8[r][4] = f2.x; a8[r][5] = f2.y; a8[r][6] = f3.x; a8[r][7] = f3.y;
            } else {
                float4 v0 = ok[r] ? *(const float4*)(Ain + (size_t)(row0 + r) * K + k0)
                                  : make_float4(0.f, 0.f, 0.f, 0.f);
                float4 v1 = ok[r] ? *(const float4*)(Ain + (size_t)(row0 + r) * K + k0 + 4)
                                  : make_float4(0.f, 0.f, 0.f, 0.f);
                a8[r][0] = v0.x; a8[r][1] = v0.y; a8[r][2] = v0.z; a8[r][3] = v0.w;
                a8[r][4] = v1.x; a8[r][5] = v1.y; a8[r][6] = v1.z; a8[r][7] = v1.w;
            }
        }
#pragma unroll
        for (int kk = 0; kk < 8; kk++) {
            float4 w0 = *(const float4*)(sW + (k0 + kk) * 64 + cc * 8);
            float4 w1 = *(const float4*)(sW + (k0 + kk) * 64 + cc * 8 + 4);
#pragma unroll
            for (int r = 0; r < 4; r++) {
                float av = a8[r][kk];
                acc[r][0] = fmaf(av, w0.x, acc[r][0]);
                acc[r][1] = fmaf(av, w0.y, acc[r][1]);
                acc[r][2] = fmaf(av, w0.z, acc[r][2]);
                acc[r][3] = fmaf(av, w0.w, acc[r][3]);
                acc[r][4] = fmaf(av, w1.x, acc[r][4]);
                acc[r][5] = fmaf(av, w1.y, acc[r][5]);
                acc[r][6] = fmaf(av, w1.z, acc[r][6]);
                acc[r][7] = fmaf(av, w1.w, acc[r][7]);
            }
        }
    }

#pragma unroll
    for (int r = 0; r < 4; r++) {
        if (!ok[r]) continue;
        float d = g_dis[row0 + r];
        uint4 o;
        __half2 h0 = __floats2half2_rn(acc[r][0] * d, acc[r][1] * d);
        __half2 h1 = __floats2half2_rn(acc[r][2] * d, acc[r][3] * d);
        __half2 h2 = __floats2half2_rn(acc[r][4] * d, acc[r][5] * d);
        __half2 h3 = __floats2half2_rn(acc[r][6] * d, acc[r][7] * d);
        o.x = *(unsigned*)&h0; o.y = *(unsigned*)&h1;
        o.z = *(unsigned*)&h2; o.w = *(unsigned*)&h3;
        *(uint4*)(g_h + (size_t)(row0 + r) * 64 + cc * 8) = o;
    }
}

// ---------------- aggregation: warp per dst node, quarter-warp gather -------
// out[i] = relu( dis[i] * (h'[i] + sum_{src} h'[src]) + bias )
// Row = 128B fp16. Lanes: sub = lane>>3 picks one of 4 edge slots, li = lane&7
// picks a 16B chunk -> one LDG.128 per warp gathers FOUR complete rows.
// Edge groups are processed 4 at a time from a 16B-aligned base with per-slot
// predication (no peel loops). Final cross-sub combine via two shfl_xor adds.
// FC=true applies the 64->4 FC + bfc and writes float4 per node.
template <bool FC>
__global__ void __launch_bounds__(256) k_agg(const float* __restrict__ bias,
                                             const float* __restrict__ Wfc,
                                             const float* __restrict__ bfc,
                                             float* __restrict__ out, int n) {
    int w = (blockIdx.x * 256 + threadIdx.x) >> 5;
    int lane = threadIdx.x & 31;
    if (w >= n) return;
    int sub = lane >> 3, li = lane & 7;

    int start = w ? (__ldg(&g_rptr[w - 1]) + __ldg(&g_bsum[(w - 1) >> 10])) : 0;
    int end = __ldg(&g_rptr[w]) + __ldg(&g_bsum[w >> 10]);

    const uint4* __restrict__ H4 = (const uint4*)g_h;   // 8 uint4 per row

    float acc[8];
#pragma unroll
    for (int j = 0; j < 8; j++) acc[j] = 0.f;

    // self loop contribution (sub 0 only; combined later by the xor-reduce)
    if (sub == 0) {
        uint4 v = H4[(size_t)w * 8 + li];
        const __half2* hv = (const __half2*)&v;
#pragma unroll
        for (int j = 0; j < 4; j++) {
            float2 f = __half22float2(hv[j]);
            acc[2 * j] += f.x;
            acc[2 * j + 1] += f.y;
        }
    }

    for (int e = start & ~3; e < end; e += 4) {
        int4 cs = *(const int4*)(g_col + e);   // 16B-aligned broadcast LDG.128
        int idx = e + sub;
        if (idx >= start && idx < end) {
            int s = (sub == 0) ? cs.x : (sub == 1) ? cs.y : (sub == 2) ? cs.z : cs.w;
            uint4 v = H4[(size_t)s * 8 + li];
            const __half2* hv = (const __half2*)&v;
#pragma unroll
            for (int j = 0; j < 4; j++) {
                float2 f = __half22float2(hv[j]);
                acc[2 * j] += f.x;
                acc[2 * j + 1] += f.y;
            }
        }
    }

    // combine the 4 edge-slot partial sums (lanes with equal li)
#pragma unroll
    for (int j = 0; j < 8; j++) {
        acc[j] += __shfl_xor_sync(0xffffffffu, acc[j], 16);
        acc[j] += __shfl_xor_sync(0xffffffffu, acc[j], 8);
    }

    float d = __ldg(&g_dis[w]);

    if (!FC) {
        if (sub == 0) {
            float4 b0 = *(const float4*)(bias + li * 8);
            float4 b1 = *(const float4*)(bias + li * 8 + 4);
            __half2 hbuf[4];
            hbuf[0] = __floats2half2_rn(fmaxf(fmaf(acc[0], d, b0.x), 0.f),
                                        fmaxf(fmaf(acc[1], d, b0.y), 0.f));
            hbuf[1] = __floats2half2_rn(fmaxf(fmaf(acc[2], d, b0.z), 0.f),
                                        fmaxf(fmaf(acc[3], d, b0.w), 0.f));
            hbuf[2] = __floats2half2_rn(fmaxf(fmaf(acc[4], d, b1.x), 0.f),
                                        fmaxf(fmaf(acc[5], d, b1.y), 0.f));
            hbuf[3] = __floats2half2_rn(fmaxf(fmaf(acc[6], d, b1.z), 0.f),
                                        fmaxf(fmaf(acc[7], d, b1.w), 0.f));
            *(uint4*)(g_a + (size_t)w * 64 + li * 8) = *(uint4*)hbuf;
        }
    } else {
        if (sub == 0) {
            float4 b0 = *(const float4*)(bias + li * 8);
            float4 b1 = *(const float4*)(bias + li * 8 + 4);
            float o[8];
            o[0] = fmaxf(fmaf(acc[0], d, b0.x), 0.f);
            o[1] = fmaxf(fmaf(acc[1], d, b0.y), 0.f);
            o[2] = fmaxf(fmaf(acc[2], d, b0.z), 0.f);
            o[3] = fmaxf(fmaf(acc[3], d, b0.w), 0.f);
            o[4] = fmaxf(fmaf(acc[4], d, b1.x), 0.f);
            o[5] = fmaxf(fmaf(acc[5], d, b1.y), 0.f);
            o[6] = fmaxf(fmaf(acc[6], d, b1.z), 0.f);
            o[7] = fmaxf(fmaf(acc[7], d, b1.w), 0.f);
            float4 y = make_float4(0.f, 0.f, 0.f, 0.f);
            const float4* Wf = (const float4*)Wfc;   // [64][4]
#pragma unroll
            for (int j = 0; j < 8; j++) {
                float4 wr = Wf[li * 8 + j];
                y.x = fmaf(o[j], wr.x, y.x);
                y.y = fmaf(o[j], wr.y, y.y);
                y.z = fmaf(o[j], wr.z, y.z);
                y.w = fmaf(o[j], wr.w, y.w);
            }
#pragma unroll
            for (int off = 4; off; off >>= 1) {
                y.x += __shfl_xor_sync(0xffffffffu, y.x, off);
                y.y += __shfl_xor_sync(0xffffffffu, y.y, off);
                y.z += __shfl_xor_sync(0xffffffffu, y.z, off);
                y.w += __shfl_xor_sync(0xffffffffu, y.w, off);
            }
            if (li == 0) {
                float4 bf = *(const float4*)bfc;
                ((float4*)out)[w] = make_float4(y.x + bf.x, y.y + bf.y,
                                                y.z + bf.z, y.w + bf.w);
            }
        }
    }
}

// ---------------- launch ----------------------------------------------------

extern "C" void kernel_launch(void* const* d_in, const int* in_sizes, int n_in,
                              void* d_out, int out_size) {
    const float* x   = (const float*)d_in[0];
    const int*   ei  = (const int*)d_in[1];
    const float* W1  = (const float*)d_in[2];
    const float* b1  = (const float*)d_in[3];
    const float* W2  = (const float*)d_in[4];
    const float* b2  = (const float*)d_in[5];
    const float* Wfc = (const float*)d_in[6];
    const float* bfc = (const float*)d_in[7];

    int n = in_sizes[0] / 128;
    int E = in_sizes[1] / 2;
    if (n > NMAX) n = NMAX;
    if (E > ECAP) E = ECAP;
    const int* src = ei;
    const int* dst = ei + E;
    int nb = (n + 1023) / 1024;
    int e4b = (E / 4 + 256) / 256;   // blocks for 4-wide edge kernels (covers remainder)

    // one-time side stream + events (resource init only; no per-call work change)
    static cudaStream_t sB = nullptr;
    static cudaEvent_t evFork = nullptr, evJoin = nullptr;
    if (!sB) {
        cudaStreamCreateWithFlags(&sB, cudaStreamNonBlocking);
        cudaEventCreateWithFlags(&evFork, cudaEventDisableTiming);
        cudaEventCreateWithFlags(&evJoin, cudaEventDisableTiming);
    }

    void* cnt_ptr = nullptr;
    cudaGetSymbolAddress(&cnt_ptr, g_cnt);
    cudaMemsetAsync(cnt_ptr, 0, (size_t)n * sizeof(int));

    k_hist<<<e4b, 256>>>(dst, E);
    k_scan1<<<nb, 1024>>>(n);

    // fork: gemm1 depends only on scan1 (dis); overlaps scan2 + fill
    cudaEventRecord(evFork, 0);
    cudaStreamWaitEvent(sB, evFork, 0);
    k_gemm<128, false><<<(n + 127) / 128, 256, 0, sB>>>(x, W1, n);
    cudaEventRecord(evJoin, sB);

    k_scan2<<<1, 1024>>>(nb);
    k_fill<<<e4b, 256>>>(src, dst, E);

    cudaStreamWaitEvent(0, evJoin, 0);   // join before agg1 reads g_h

    k_agg<false><<<(n + 7) / 8, 256>>>(b1, nullptr, nullptr, nullptr, n);
    k_gemm<64, true><<<(n + 127) / 128, 256>>>(nullptr, W2, n);
    k_agg<true><<<(n + 7) / 8, 256>>>(b2, Wfc, bfc, (float*)d_out, n);
}

// round 6
// speedup vs baseline: 1.3646x; 1.3071x over previous
#include <cuda_runtime.h>
#include <cuda_fp16.h>

// ---------------- scratch (device globals; no allocation allowed) ----------
#define NMAX  100032
#define ECAP  1664000

__device__ __half g_h [NMAX * 64];   // GEMM output (pre-scaled by dis[row]), fp16
__device__ __half g_a [NMAX * 64];   // post-aggregation activations, fp16
__device__ float  g_dis[NMAX];
__device__ int    g_cnt[NMAX];
__device__ int    g_rptr[NMAX];      // after fill: block-local inclusive prefix
__device__ int    g_col[ECAP];
__device__ int    g_bsum[128];       // exclusive scan of block totals (carry)

// ---------------- preprocessing kernels ------------------------------------

__global__ void k_hist(const int* __restrict__ dst, int E) {
    int e = (blockIdx.x * 256 + threadIdx.x) * 4;
    if (e + 4 <= E) {
        int4 d = *(const int4*)(dst + e);
        atomicAdd(&g_cnt[d.x], 1);
        atomicAdd(&g_cnt[d.y], 1);
        atomicAdd(&g_cnt[d.z], 1);
        atomicAdd(&g_cnt[d.w], 1);
    } else {
        for (; e < E; e++) atomicAdd(&g_cnt[dst[e]], 1);
    }
}

// block-wide exclusive scan helper (blockDim.x == 1024)
__device__ __forceinline__ int blockscan_excl(int v, int* total) {
    __shared__ int ws[32];
    int lane = threadIdx.x & 31, wid = threadIdx.x >> 5;
    int s = v;
#pragma unroll
    for (int o = 1; o < 32; o <<= 1) {
        int t = __shfl_up_sync(0xffffffffu, s, o);
        if (lane >= o) s += t;
    }
    if (lane == 31) ws[wid] = s;
    __syncthreads();
    if (wid == 0) {
        int u = ws[lane];
#pragma unroll
        for (int o = 1; o < 32; o <<= 1) {
            int t = __shfl_up_sync(0xffffffffu, u, o);
            if (lane >= o) u += t;
        }
        ws[lane] = u;
    }
    __syncthreads();
    int incl = s + (wid ? ws[wid - 1] : 0);
    if (total) *total = ws[31];
    return incl - v;
}

// per-block exclusive scan of cnt -> rptr (local), block totals -> bsum,
// fused with dis = rsqrt(deg+1)
__global__ void k_scan1(int n) {
    int i = blockIdx.x * 1024 + threadIdx.x;
    int v = (i < n) ? g_cnt[i] : 0;
    int tot;
    int ex = blockscan_excl(v, &tot);
    if (i < n) {
        g_rptr[i] = ex;
        g_dis[i] = rsqrtf((float)(v + 1));   // +1 self loop; always > 0
    }
    if (threadIdx.x == 0) g_bsum[blockIdx.x] = tot;
}

// exclusive scan of block sums (single block)
__global__ void k_scan2(int nb) {
    int i = threadIdx.x;
    int v = (i < nb) ? g_bsum[i] : 0;   // reads complete before writes (barrier in scan)
    int ex = blockscan_excl(v, nullptr);
    if (i < nb) g_bsum[i] = ex;
}

// CSR fill. Slot = local post-increment + block carry.
__global__ void k_fill(const int* __restrict__ src, const int* __restrict__ dst, int E) {
    int e = (blockIdx.x * 256 + threadIdx.x) * 4;
    if (e + 4 <= E) {
        int4 d = *(const int4*)(dst + e);
        int4 s = *(const int4*)(src + e);
        g_col[atomicAdd(&g_rptr[d.x], 1) + g_bsum[d.x >> 10]] = s.x;
        g_col[atomicAdd(&g_rptr[d.y], 1) + g_bsum[d.y >> 10]] = s.y;
        g_col[atomicAdd(&g_rptr[d.z], 1) + g_bsum[d.z >> 10]] = s.z;
        g_col[atomicAdd(&g_rptr[d.w], 1) + g_bsum[d.w >> 10]] = s.w;
    } else {
        for (; e < E; e++) {
            int d = dst[e];
            g_col[atomicAdd(&g_rptr[d], 1) + g_bsum[d >> 10]] = src[e];
        }
    }
}

// ---------------- GEMM via mma.sync (HMMA), split-fp16 = fp32 accuracy ------
// H[n,64] = (A[n,K] @ W[K,64]) * dis[row]  -> fp16 g_h
// Block: 64 rows x 64 cols, 8 warps (wm = wid&3 row-tile, wn = wid>>2 col-half).
// Warp tile: 16 rows x 32 cols = 4 n-fragments of m16n8k16.
// !HALF_IN: A = fp32 x, split into hi+lo fp16 in smem; W split hi+lo:
//   D = Ah*Wh + Ah*Wl + Al*Wh   (dropped Al*Wl ~ eps^2 ~ 6e-8)
// HALF_IN:  A = g_a (exact fp16); D = A*Wh + A*Wl (numerically == fp32 gemm).
// W staged TRANSPOSED in smem (WT[n][k]) so B-fragment k-pairs are contiguous.
__device__ __forceinline__ void mma16816(float acc[4], const unsigned a[4],
                                         const unsigned b[2]) {
    asm volatile(
        "mma.sync.aligned.m16n8k16.row.col.f32.f16.f16.f32 "
        "{%0,%1,%2,%3}, {%4,%5,%6,%7}, {%8,%9}, {%0,%1,%2,%3};\n"
        : "+f"(acc[0]), "+f"(acc[1]), "+f"(acc[2]), "+f"(acc[3])
        : "r"(a[0]), "r"(a[1]), "r"(a[2]), "r"(a[3]), "r"(b[0]), "r"(b[1]));
}

template <int K, bool HALF_IN>
__global__ void __launch_bounds__(256) k_gemm_mma(const float* __restrict__ Ain,
                                                  const float* __restrict__ W, int n) {
    constexpr int LD = K + 8;        // halves per row (even; rows 4B-aligned)
    extern __shared__ __align__(16) char dyn[];
    __half* sWh = (__half*)dyn;              // [64][LD]  W^T hi
    __half* sWl = sWh + 64 * LD;             // [64][LD]  W^T lo
    __half* sAh = sWl + 64 * LD;             // [64][LD]  A hi (or exact A)
    __half* sAl = sAh + 64 * LD;             // [64][LD]  A lo (layer-1 only)

    int tid = threadIdx.x;
    int wid = tid >> 5, lane = tid & 31;
    int wm = wid & 3, wn = wid >> 2;
    int row0 = blockIdx.x * 64;

    // stage W transposed, hi/lo split
    for (int i = tid; i < K * 64; i += 256) {
        int k = i >> 6, nn = i & 63;
        float w = W[i];
        __half h = __float2half_rn(w);
        sWh[nn * LD + k] = h;
        sWl[nn * LD + k] = __float2half_rn(w - __half2float(h));
    }

    // stage A
    if (HALF_IN) {
        // exact fp16 copy from g_a (NMAX is a multiple of 64: no OOB reads)
        for (int i = tid; i < 64 * (K / 8); i += 256) {
            int row = i / (K / 8), c8 = i % (K / 8);
            uint4 v = *(const uint4*)(g_a + (size_t)(row0 + row) * K + c8 * 8);
            *(uint4*)(sAh + row * LD + c8 * 8) = v;
        }
    } else {
        for (int i = tid; i < 64 * (K / 4); i += 256) {
            int row = i / (K / 4), c4 = i % (K / 4);
            int grow = row0 + row;
            float4 v = (grow < n) ? *(const float4*)(Ain + (size_t)grow * K + c4 * 4)
                                  : make_float4(0.f, 0.f, 0.f, 0.f);
            __half hx = __float2half_rn(v.x), hy = __float2half_rn(v.y);
            __half hz = __float2half_rn(v.z), hw = __float2half_rn(v.w);
            __half* ph = sAh + row * LD + c4 * 4;
            ph[0] = hx; ph[1] = hy; ph[2] = hz; ph[3] = hw;
            __half* pl = sAl + row * LD + c4 * 4;
            pl[0] = __float2half_rn(v.x - __half2float(hx));
            pl[1] = __float2half_rn(v.y - __half2float(hy));
            pl[2] = __float2half_rn(v.z - __half2float(hz));
            pl[3] = __float2half_rn(v.w - __half2float(hw));
        }
    }
    __syncthreads();

    float acc[4][4];
#pragma unroll
    for (int f = 0; f < 4; f++)
#pragma unroll
        for (int j = 0; j < 4; j++) acc[f][j] = 0.f;

    int g = lane >> 2, t = lane & 3;

#pragma unroll
    for (int ks = 0; ks < K / 16; ks++) {
        int kk = ks * 16 + t * 2;
        int r = wm * 16 + g;
        unsigned ah[4], al[4];
        ah[0] = *(const unsigned*)(sAh + r * LD + kk);
        ah[1] = *(const unsigned*)(sAh + (r + 8) * LD + kk);
        ah[2] = *(const unsigned*)(sAh + r * LD + kk + 8);
        ah[3] = *(const unsigned*)(sAh + (r + 8) * LD + kk + 8);
        if (!HALF_IN) {
            al[0] = *(const unsigned*)(sAl + r * LD + kk);
            al[1] = *(const unsigned*)(sAl + (r + 8) * LD + kk);
            al[2] = *(const unsigned*)(sAl + r * LD + kk + 8);
            al[3] = *(const unsigned*)(sAl + (r + 8) * LD + kk + 8);
        }
#pragma unroll
        for (int nf = 0; nf < 4; nf++) {
            int nn = wn * 32 + nf * 8 + g;
            unsigned bh[2], bl[2];
            bh[0] = *(const unsigned*)(sWh + nn * LD + kk);
            bh[1] = *(const unsigned*)(sWh + nn * LD + kk + 8);
            bl[0] = *(const unsigned*)(sWl + nn * LD + kk);
            bl[1] = *(const unsigned*)(sWl + nn * LD + kk + 8);
            mma16816(acc[nf], ah, bh);
            mma16816(acc[nf], ah, bl);
            if (!HALF_IN) mma16816(acc[nf], al, bh);
        }
    }

    // epilogue: scale by dis[row], store fp16
    int r0 = row0 + wm * 16 + g, r1 = r0 + 8;
    float d0 = (r0 < n) ? g_dis[r0] : 0.f;
    float d1 = (r1 < n) ? g_dis[r1] : 0.f;
#pragma unroll
    for (int nf = 0; nf < 4; nf++) {
        int col = wn * 32 + nf * 8 + t * 2;
        if (r0 < n)
            *(__half2*)(g_h + (size_t)r0 * 64 + col) =
                __floats2half2_rn(acc[nf][0] * d0, acc[nf][1] * d0);
        if (r1 < n)
            *(__half2*)(g_h + (size_t)r1 * 64 + col) =
                __floats2half2_rn(acc[nf][2] * d1, acc[nf][3] * d1);
    }
}

// ---------------- aggregation: warp per dst node (R2 body) ------------------
// out[i] = relu( dis[i] * (h'[i] + sum_{src in nbrs} h'[src]) + bias )
// h' rows are fp16 (128B/row, one half2 per lane). Accumulate fp32.
// FC=true additionally applies the 64->4 FC + bfc and writes float4 per node.
template <bool FC>
__global__ void __launch_bounds__(256) k_agg(const float* __restrict__ bias,
                                             const float* __restrict__ Wfc,
                                             const float* __restrict__ bfc,
                                             float* __restrict__ out, int n) {
    int w = (blockIdx.x * 256 + threadIdx.x) >> 5;
    int lane = threadIdx.x & 31;
    if (w >= n) return;

    int start = w ? (__ldg(&g_rptr[w - 1]) + __ldg(&g_bsum[(w - 1) >> 10])) : 0;
    int end = __ldg(&g_rptr[w]) + __ldg(&g_bsum[w >> 10]);

    const __half2* __restrict__ H2 = (const __half2*)g_h;
    float2 acc = __half22float2(H2[(size_t)w * 32 + lane]);   // self loop

    int e = start;
    for (; e + 4 <= end; e += 4) {
        int s0 = __ldg(&g_col[e]), s1 = __ldg(&g_col[e + 1]);
        int s2 = __ldg(&g_col[e + 2]), s3 = __ldg(&g_col[e + 3]);
        float2 v0 = __half22float2(H2[(size_t)s0 * 32 + lane]);
        float2 v1 = __half22float2(H2[(size_t)s1 * 32 + lane]);
        float2 v2 = __half22float2(H2[(size_t)s2 * 32 + lane]);
        float2 v3 = __half22float2(H2[(size_t)s3 * 32 + lane]);
        acc.x += (v0.x + v1.x) + (v2.x + v3.x);
        acc.y += (v0.y + v1.y) + (v2.y + v3.y);
    }
    for (; e < end; e++) {
        float2 v = __half22float2(H2[(size_t)__ldg(&g_col[e]) * 32 + lane]);
        acc.x += v.x;
        acc.y += v.y;
    }

    float d = g_dis[w];
    float2 b = ((const float2*)bias)[lane];
    float ox = fmaxf(fmaf(acc.x, d, b.x), 0.f);
    float oy = fmaxf(fmaf(acc.y, d, b.y), 0.f);

    if (!FC) {
        ((__half2*)g_a)[(size_t)w * 32 + lane] = __floats2half2_rn(ox, oy);
    } else {
        const float4* Wf = (const float4*)Wfc;   // [64][4]
        float4 w0 = Wf[2 * lane], w1 = Wf[2 * lane + 1];
        float4 y;
        y.x = ox * w0.x + oy * w1.x;
        y.y = ox * w0.y + oy * w1.y;
        y.z = ox * w0.z + oy * w1.z;
        y.w = ox * w0.w + oy * w1.w;
#pragma unroll
        for (int o = 16; o; o >>= 1) {
            y.x += __shfl_xor_sync(0xffffffffu, y.x, o);
            y.y += __shfl_xor_sync(0xffffffffu, y.y, o);
            y.z += __shfl_xor_sync(0xffffffffu, y.z, o);
            y.w += __shfl_xor_sync(0xffffffffu, y.w, o);
        }
        if (lane == 0) {
            float4 bf = *(const float4*)bfc;
            ((float4*)out)[w] = make_float4(y.x + bf.x, y.y + bf.y, y.z + bf.z, y.w + bf.w);
        }
    }
}

// ---------------- launch ----------------------------------------------------

extern "C" void kernel_launch(void* const* d_in, const int* in_sizes, int n_in,
                              void* d_out, int out_size) {
    const float* x   = (const float*)d_in[0];
    const int*   ei  = (const int*)d_in[1];
    const float* W1  = (const float*)d_in[2];
    const float* b1  = (const float*)d_in[3];
    const float* W2  = (const float*)d_in[4];
    const float* b2  = (const float*)d_in[5];
    const float* Wfc = (const float*)d_in[6];
    const float* bfc = (const float*)d_in[7];

    int n = in_sizes[0] / 128;
    int E = in_sizes[1] / 2;
    if (n > NMAX) n = NMAX;
    if (E > ECAP) E = ECAP;
    const int* src = ei;
    const int* dst = ei + E;
    int nb = (n + 1023) / 1024;
    int e4b = (E / 4 + 256) / 256;

    // smem: layer1 = 4 planes of 64*(128+8) halves; layer2 = 3 planes of 64*(64+8)
    const int SM1 = 4 * 64 * (128 + 8) * 2;   // 69632
    const int SM2 = 3 * 64 * (64 + 8) * 2;    // 27648
    cudaFuncSetAttribute(k_gemm_mma<128, false>,
                         cudaFuncAttributeMaxDynamicSharedMemorySize, SM1);
    cudaFuncSetAttribute(k_gemm_mma<64, true>,
                         cudaFuncAttributeMaxDynamicSharedMemorySize, SM2);

    void* cnt_ptr = nullptr;
    cudaGetSymbolAddress(&cnt_ptr, g_cnt);
    cudaMemsetAsync(cnt_ptr, 0, (size_t)n * sizeof(int));

    k_hist<<<e4b, 256>>>(dst, E);
    k_scan1<<<nb, 1024>>>(n);
    k_scan2<<<1, 1024>>>(nb);
    k_fill<<<e4b, 256>>>(src, dst, E);

    int gb = (n + 63) / 64;
    k_gemm_mma<128, false><<<gb, 256, SM1>>>(x, W1, n);
    k_agg<false><<<(n + 7) / 8, 256>>>(b1, nullptr, nullptr, nullptr, n);
    k_gemm_mma<64, true><<<gb, 256, SM2>>>(nullptr, W2, n);
    k_agg<true><<<(n + 7) / 8, 256>>>(b2, Wfc, bfc, (float*)d_out, n);
}